// round 9
// baseline (speedup 1.0000x reference)
#include <cuda_runtime.h>
#include <cuda_fp16.h>
#include <mma.h>
#include <cstdint>
#include <cstddef>

using namespace nvcuda;

#define S_DIM 2048
#define DIN 4096
#define DOUT 11008
#define REMAINED 3852

// Eigen multithread-branch blocking: kc = 320. Panels joined after c = 19,39,...,239.
#define KC_BLOCKS 20

// Flag threshold: fast-sum vs exact-chain divergence bound (~20 sigma).
#define T_FLAG 1.5e-6f

// Output layout (float32 concat): tv | filtered_W | filtered_bias | indices
#define OFF_TV   ((size_t)0)
#define N_TV     ((size_t)S_DIM * DOUT)
#define OFF_W    (N_TV)
#define N_W      ((size_t)REMAINED * DIN)
#define OFF_BIAS (OFF_W + N_W)
#define OFF_IDX  (OFF_BIAS + REMAINED)

// Scratch (device globals — no allocation allowed)
__device__ int g_counts[DOUT];
__device__ int g_pos;
__device__ int g_limit;
__device__ int g_indices[REMAINED];
__device__ float g_sfast[(size_t)S_DIM * DOUT];   // fast-GEMM raw f32 sums

// ---------------------------------------------------------------------------
__global__ void init_kernel() {
    int i = blockIdx.x * blockDim.x + threadIdx.x;
    if (i < DOUT) g_counts[i] = 0;
    if (i == 0) g_pos = 0;
}

// ---------------------------------------------------------------------------
// FAST GEMM: f16 wmma, f32 accumulate. Products are EXACT (inputs f16-exact);
// only the summation order differs from the reference chain. Writes raw f32
// sum to g_sfast, provisional tv to out, counts pos.
// ---------------------------------------------------------------------------
#define BM 128
#define BN 128
#define BK 32
#define APAD 40

__global__ void gemm_fast_kernel(const float* __restrict__ x,
                                 const float* __restrict__ w,
                                 const float* __restrict__ bias,
                                 float* __restrict__ out) {
    extern __shared__ char smem[];
    __half* As = (__half*)smem;                       // [BM][APAD]
    __half* Bs = (__half*)(smem + BM * APAD * 2);     // [BN][APAD]
    float*  Cs = (float*)smem;                        // [BM][BN] (reused)

    int tid  = threadIdx.x;
    int warp = tid >> 5;
    int wm   = warp >> 2;
    int wn   = warp & 3;
    int rowBase = blockIdx.y * BM;
    int colBase = blockIdx.x * BN;

    wmma::fragment<wmma::accumulator, 16, 16, 16, float> cfrag[4][2];
#pragma unroll
    for (int i = 0; i < 4; i++)
#pragma unroll
        for (int j = 0; j < 2; j++) wmma::fill_fragment(cfrag[i][j], 0.0f);

    for (int k0 = 0; k0 < DIN; k0 += BK) {
        __syncthreads();
#pragma unroll
        for (int l = tid; l < 1024; l += 256) {
            int r = l >> 3, c = (l & 7) * 4;
            float4 va = *(const float4*)(x + (size_t)(rowBase + r) * DIN + k0 + c);
            float4 vb = *(const float4*)(w + (size_t)(colBase + r) * DIN + k0 + c);
            uint2 pa, pb;
            ((__half2*)&pa)[0] = __floats2half2_rn(va.x, va.y);
            ((__half2*)&pa)[1] = __floats2half2_rn(va.z, va.w);
            ((__half2*)&pb)[0] = __floats2half2_rn(vb.x, vb.y);
            ((__half2*)&pb)[1] = __floats2half2_rn(vb.z, vb.w);
            *(uint2*)(As + r * APAD + c) = pa;
            *(uint2*)(Bs + r * APAD + c) = pb;
        }
        __syncthreads();
#pragma unroll
        for (int kk = 0; kk < BK; kk += 16) {
            wmma::fragment<wmma::matrix_a, 16, 16, 16, __half, wmma::row_major> afrag[4];
            wmma::fragment<wmma::matrix_b, 16, 16, 16, __half, wmma::col_major> bfrag[2];
#pragma unroll
            for (int i = 0; i < 4; i++)
                wmma::load_matrix_sync(afrag[i], As + (wm * 64 + i * 16) * APAD + kk, APAD);
#pragma unroll
            for (int j = 0; j < 2; j++)
                wmma::load_matrix_sync(bfrag[j], Bs + (wn * 32 + j * 16) * APAD + kk, APAD);
#pragma unroll
            for (int i = 0; i < 4; i++)
#pragma unroll
                for (int j = 0; j < 2; j++)
                    wmma::mma_sync(cfrag[i][j], afrag[i], bfrag[j], cfrag[i][j]);
        }
    }
    __syncthreads();
#pragma unroll
    for (int i = 0; i < 4; i++)
#pragma unroll
        for (int j = 0; j < 2; j++)
            wmma::store_matrix_sync(Cs + (wm * 64 + i * 16) * BN + wn * 32 + j * 16,
                                    cfrag[i][j], BN, wmma::mem_row_major);
    __syncthreads();

    int pos = 0;
#pragma unroll 4
    for (int e = 0; e < 64; e++) {
        int lin = tid + 256 * e;
        int r = lin >> 7, c = lin & 127;
        int row = rowBase + r, col = colBase + c;
        float acc = Cs[lin];
        g_sfast[(size_t)row * DOUT + col] = acc;
        __half hmm = __float2half(acc);
        float tvf = __half2float(hmm) + bias[col];
        __half h = __float2half(tvf);
        float hv = __half2float(h);
        out[OFF_TV + (size_t)row * DOUT + col] = hv;
        pos += (hv > 0.0f) ? 1 : 0;
    }
#pragma unroll
    for (int off = 16; off; off >>= 1) pos += __shfl_down_sync(~0u, pos, off);
    __shared__ int spos[8];
    if ((tid & 31) == 0) spos[warp] = pos;
    __syncthreads();
    if (tid == 0) {
        int t = 0;
        for (int i = 0; i < 8; i++) t += spos[i];
        atomicAdd(&g_pos, t);
    }
}

// ---------------------------------------------------------------------------
// Flag test: is the fast sum within T_FLAG of an f16 round-to-nearest midpoint?
// ---------------------------------------------------------------------------
__device__ __forceinline__ unsigned short hnext(unsigned short b) {  // toward +inf
    if (b == 0x8000u) return 0x0001u;
    return (b & 0x8000u) ? (unsigned short)(b - 1) : (unsigned short)(b + 1);
}
__device__ __forceinline__ unsigned short hprev(unsigned short b) {  // toward -inf
    if (b == 0x0000u) return 0x8001u;
    return (b & 0x8000u) ? (unsigned short)(b + 1) : (unsigned short)(b - 1);
}
__device__ __forceinline__ bool unsafe_val(float s) {
    __half h = __float2half_rn(s);
    unsigned short b = __half_as_ushort(h);
    float hv = __half2float(h);
    float up = __half2float(__ushort_as_half(hnext(b)));
    float dn = __half2float(__ushort_as_half(hprev(b)));
    float mhi = 0.5f * (hv + up);
    float mlo = 0.5f * (hv + dn);
    return (mhi - s < T_FLAG) || (s - mlo < T_FLAG);
}

// ---------------------------------------------------------------------------
// RECOMPUTE: per 128x128 tile, find flagged elements and recompute them with
// the EXACT Eigen chain (ascending k, kc=320 panel joins) — bit-identical to
// the round-7 kernel. Fix tv and g_pos.
// Block 512 threads. Waves of 4096 elements (8 per thread) if a tile overflows.
// ---------------------------------------------------------------------------
#define MAXPE 8
#define WAVE (512 * MAXPE)
#define XH_STRIDE 20   // halves per row (40B, 8B-aligned stores)

__global__ void __launch_bounds__(512) recompute_kernel(
        const float* __restrict__ x,
        const float* __restrict__ w,
        const float* __restrict__ bias,
        float* __restrict__ out) {
    __shared__ unsigned short list[16384];
    __shared__ __half xs_h[128 * XH_STRIDE];
    __shared__ __half ws_h[128 * XH_STRIDE];
    __shared__ int scnt;

    int tid = threadIdx.x;
    int rowBase = blockIdx.y * 128;
    int colBase = blockIdx.x * 128;

    if (tid == 0) scnt = 0;
    __syncthreads();

    // Phase 1: scan tile of g_sfast, collect flagged elements
    for (int e = 0; e < 32; e++) {
        int lin = tid + 512 * e;
        int r = lin >> 7, c = lin & 127;
        float s = g_sfast[(size_t)(rowBase + r) * DOUT + colBase + c];
        if (unsafe_val(s)) {
            int idx = atomicAdd(&scnt, 1);
            list[idx] = (unsigned short)lin;
        }
    }
    __syncthreads();
    int cnt = scnt;
    if (cnt == 0) return;

    int r0 = tid >> 2;   // staging row 0..127
    int q0 = tid & 3;    // staging k-quarter
    int posDelta = 0;

    for (int base = 0; base < cnt; base += WAVE) {
        // assign up to MAXPE elements per thread
        int rl[MAXPE], cl[MAXPE];
        float accT[MAXPE], accC[MAXPE];
#pragma unroll
        for (int p = 0; p < MAXPE; p++) {
            int idx = base + p * 512 + tid;
            if (idx < cnt) {
                int lin = list[idx];
                rl[p] = lin >> 7; cl[p] = lin & 127;
            } else rl[p] = -1;
            accT[p] = 0.0f; accC[p] = 0.0f;
        }

        // prologue: stage chunk 0
        float4 xr = *(const float4*)(x + (size_t)(rowBase + r0) * DIN + q0 * 4);
        float4 wr = *(const float4*)(w + (size_t)(colBase + r0) * DIN + q0 * 4);
        {
            uint2 pa, pb;
            ((__half2*)&pa)[0] = __floats2half2_rn(xr.x, xr.y);
            ((__half2*)&pa)[1] = __floats2half2_rn(xr.z, xr.w);
            ((__half2*)&pb)[0] = __floats2half2_rn(wr.x, wr.y);
            ((__half2*)&pb)[1] = __floats2half2_rn(wr.z, wr.w);
            *(uint2*)&xs_h[r0 * XH_STRIDE + q0 * 4] = pa;
            *(uint2*)&ws_h[r0 * XH_STRIDE + q0 * 4] = pb;
        }
        __syncthreads();

        for (int c = 0; c < 256; c++) {
            if (c + 1 < 256) {
                int k0 = (c + 1) * 16;
                xr = *(const float4*)(x + (size_t)(rowBase + r0) * DIN + k0 + q0 * 4);
                wr = *(const float4*)(w + (size_t)(colBase + r0) * DIN + k0 + q0 * 4);
            }
            // exact ascending-k chain for each assigned element
#pragma unroll
            for (int p = 0; p < MAXPE; p++) {
                if (rl[p] >= 0) {
                    const __half* xp = &xs_h[rl[p] * XH_STRIDE];
                    const __half* wp = &ws_h[cl[p] * XH_STRIDE];
#pragma unroll
                    for (int kq = 0; kq < 8; kq++) {
                        float2 xf = __half22float2(*(const __half2*)(xp + kq * 2));
                        float2 wf = __half22float2(*(const __half2*)(wp + kq * 2));
                        accC[p] = __fmaf_rn(xf.x, wf.x, accC[p]);
                        accC[p] = __fmaf_rn(xf.y, wf.y, accC[p]);
                    }
                }
            }
            if (c % KC_BLOCKS == (KC_BLOCKS - 1) && c < 240) {
#pragma unroll
                for (int p = 0; p < MAXPE; p++) {
                    accT[p] = accT[p] + accC[p];
                    accC[p] = 0.0f;
                }
            }
            __syncthreads();
            if (c + 1 < 256) {
                uint2 pa, pb;
                ((__half2*)&pa)[0] = __floats2half2_rn(xr.x, xr.y);
                ((__half2*)&pa)[1] = __floats2half2_rn(xr.z, xr.w);
                ((__half2*)&pb)[0] = __floats2half2_rn(wr.x, wr.y);
                ((__half2*)&pb)[1] = __floats2half2_rn(wr.z, wr.w);
                *(uint2*)&xs_h[r0 * XH_STRIDE + q0 * 4] = pa;
                *(uint2*)&ws_h[r0 * XH_STRIDE + q0 * 4] = pb;
                __syncthreads();
            }
        }
        // tail panel + epilogue per element
#pragma unroll
        for (int p = 0; p < MAXPE; p++) {
            if (rl[p] >= 0) {
                float st = accT[p] + accC[p];
                int row = rowBase + rl[p], col = colBase + cl[p];
                __half hmm = __float2half(st);
                float tvf = __half2float(hmm) + bias[col];
                __half h = __float2half(tvf);
                float hv = __half2float(h);
                size_t o = OFF_TV + (size_t)row * DOUT + col;
                float old = out[o];
                posDelta += ((hv > 0.0f) ? 1 : 0) - ((old > 0.0f) ? 1 : 0);
                out[o] = hv;
            }
        }
        __syncthreads();
    }
#pragma unroll
    for (int off = 16; off; off >>= 1) posDelta += __shfl_down_sync(~0u, posDelta, off);
    if ((tid & 31) == 0 && posDelta != 0) atomicAdd(&g_pos, posDelta);
}

// ---------------------------------------------------------------------------
__global__ void limit_kernel() {
    g_limit = (int)floorf((0.2f * (float)g_pos) / 2048.0f);
}

// ---------------------------------------------------------------------------
__device__ __forceinline__ unsigned key16f(float f) {
    unsigned short b = __half_as_ushort(__float2half(f));
    if (b == 0x8000u) b = 0;
    return (b & 0x8000u) ? (unsigned)(0xFFFFu ^ b) : (unsigned)(b | 0x8000u);
}

__global__ void topmask_kernel(const float* __restrict__ tv) {
    int row = blockIdx.x;
    int limit = g_limit;
    if (limit <= 0) return;

    __shared__ int hist[256];
    __shared__ int scan[256];
    __shared__ int sB, sChi, sK, sNeed;
    int tid = threadIdx.x;
    const float* tvr = tv + (size_t)row * DOUT;

    hist[tid] = 0;
    __syncthreads();
    for (int j = tid; j < DOUT; j += 256)
        atomicAdd(&hist[key16f(tvr[j]) >> 8], 1);
    __syncthreads();
    if (tid == 0) {
        int c = 0, b = 255;
        for (; b > 0; b--) {
            if (c + hist[b] >= limit) break;
            c += hist[b];
        }
        sB = b; sChi = c;
    }
    __syncthreads();
    int b = sB, chi = sChi;

    hist[tid] = 0;
    __syncthreads();
    for (int j = tid; j < DOUT; j += 256) {
        unsigned u = key16f(tvr[j]);
        if ((int)(u >> 8) == b) atomicAdd(&hist[u & 255], 1);
    }
    __syncthreads();
    if (tid == 0) {
        int c = chi, lb = 255;
        for (; lb > 0; lb--) {
            if (c + hist[lb] >= limit) break;
            c += hist[lb];
        }
        sK = (b << 8) | lb;
        sNeed = limit - c;
    }
    __syncthreads();
    unsigned K = (unsigned)sK;
    int need = sNeed;

    int j0 = tid * 43;
    int myTies = 0;
    for (int j = j0; j < j0 + 43; j++) {
        unsigned u = key16f(tvr[j]);
        if (u > K) atomicAdd(&g_counts[j], 1);
        else if (u == K) myTies++;
    }
    scan[tid] = myTies;
    __syncthreads();
    for (int off = 1; off < 256; off <<= 1) {
        int t = (tid >= off) ? scan[tid - off] : 0;
        __syncthreads();
        scan[tid] += t;
        __syncthreads();
    }
    int rank = scan[tid] - myTies;
    if (myTies > 0) {
        for (int j = j0; j < j0 + 43; j++) {
            if (key16f(tvr[j]) == K) {
                if (rank < need) atomicAdd(&g_counts[j], 1);
                rank++;
            }
        }
    }
}

// ---------------------------------------------------------------------------
__global__ void sort_kernel(const float* __restrict__ bias, float* __restrict__ out) {
    extern __shared__ unsigned keys[];
    int tid = threadIdx.x;
    for (int i = tid; i < 16384; i += 1024) {
        int cnt = (i < DOUT) ? g_counts[i] : 0;
        keys[i] = ((unsigned)cnt << 14) | (unsigned)(16383 - i);
    }
    __syncthreads();
    for (unsigned k = 2; k <= 16384; k <<= 1) {
        for (unsigned j = k >> 1; j > 0; j >>= 1) {
            for (int i = tid; i < 16384; i += 1024) {
                unsigned ixj = (unsigned)i ^ j;
                if (ixj > (unsigned)i) {
                    unsigned a = keys[i], c = keys[ixj];
                    bool desc = ((i & k) == 0);
                    if (desc ? (a < c) : (a > c)) { keys[i] = c; keys[ixj] = a; }
                }
            }
            __syncthreads();
        }
    }
    for (int i = tid; i < REMAINED; i += 1024) {
        int idx = 16383 - (int)(keys[i] & 16383u);
        g_indices[i] = idx;
        out[OFF_BIAS + i] = bias[idx];
        out[OFF_IDX + i]  = (float)idx;
    }
}

// ---------------------------------------------------------------------------
__global__ void gather_kernel(const float* __restrict__ w, float* __restrict__ out) {
    int i = blockIdx.x * blockDim.x + threadIdx.x;
    const int total8 = REMAINED * (DIN / 8);
    if (i >= total8) return;
    int r = i / (DIN / 8);
    int c8 = i % (DIN / 8);
    int src = g_indices[r];
    const float* s = w + (size_t)src * DIN + (size_t)c8 * 8;
    float* o = out + OFF_W + (size_t)r * DIN + (size_t)c8 * 8;
    float4 v0 = *(const float4*)(s);
    float4 v1 = *(const float4*)(s + 4);
    *(float4*)(o)     = v0;
    *(float4*)(o + 4) = v1;
}

// ---------------------------------------------------------------------------
extern "C" void kernel_launch(void* const* d_in, const int* in_sizes, int n_in,
                              void* d_out, int out_size) {
    const float* x    = (const float*)d_in[0];
    const float* w    = (const float*)d_in[1];
    const float* bias = (const float*)d_in[2];
    float* out = (float*)d_out;

    cudaFuncSetAttribute(gemm_fast_kernel, cudaFuncAttributeMaxDynamicSharedMemorySize, 65536);
    cudaFuncSetAttribute(sort_kernel, cudaFuncAttributeMaxDynamicSharedMemorySize, 65536);

    init_kernel<<<(DOUT + 255) / 256, 256>>>();
    gemm_fast_kernel<<<dim3(DOUT / BN, S_DIM / BM), 256, 65536>>>(x, w, bias, out);
    recompute_kernel<<<dim3(DOUT / 128, S_DIM / 128), 512>>>(x, w, bias, out);
    limit_kernel<<<1, 1>>>();
    topmask_kernel<<<S_DIM, 256>>>(out + OFF_TV);
    sort_kernel<<<1, 1024, 65536>>>(bias, out);
    gather_kernel<<<(REMAINED * (DIN / 8) + 255) / 256, 256>>>(w, out);
}

// round 10
// speedup vs baseline: 2.8665x; 2.8665x over previous
#include <cuda_runtime.h>
#include <cuda_fp16.h>
#include <mma.h>
#include <cstdint>
#include <cstddef>

using namespace nvcuda;

#define S_DIM 2048
#define DIN 4096
#define DOUT 11008
#define REMAINED 3852

#define T_FLAG 1.5e-6f     // fast-vs-exact sum divergence bound (~>20 sigma)
#define NZ_TVMAX 1e-4f     // |tv| below which a 1-ulp mm flip could change sign
#define BAND 3             // key-ulp half-width around per-row threshold K
#define LIST_CAP 131072

// Output layout (float32 concat): tv | filtered_W | filtered_bias | indices
#define OFF_TV   ((size_t)0)
#define N_TV     ((size_t)S_DIM * DOUT)
#define OFF_W    (N_TV)
#define N_W      ((size_t)REMAINED * DIN)
#define OFF_BIAS (OFF_W + N_W)
#define OFF_IDX  (OFF_BIAS + REMAINED)

// Scratch (device globals — no allocation allowed)
__device__ int g_counts[DOUT];
__device__ int g_pos;
__device__ int g_limit;
__device__ int g_indices[REMAINED];
__device__ float g_sfast[(size_t)S_DIM * DOUT];  // fast-GEMM raw f32 sums (pre-bias)
__device__ int  g_nz_cnt;
__device__ int2 g_nz[LIST_CAP];   // flagged & near-zero tv  (pos-critical)
__device__ int  g_bd_cnt;
__device__ int2 g_bd[LIST_CAP];   // flagged & near row-threshold (selection-critical)

// ---------------------------------------------------------------------------
__global__ void init_kernel() {
    int i = blockIdx.x * blockDim.x + threadIdx.x;
    if (i < DOUT) g_counts[i] = 0;
    if (i == 0) { g_pos = 0; g_nz_cnt = 0; g_bd_cnt = 0; }
}

// ---------------------------------------------------------------------------
// Flag test: is the fast sum within T_FLAG of an f16 round-to-nearest midpoint?
// (validated in round 9: flag + exact recompute reproduced exact tv bitwise)
// ---------------------------------------------------------------------------
__device__ __forceinline__ unsigned short hnext(unsigned short b) {
    if (b == 0x8000u) return 0x0001u;
    return (b & 0x8000u) ? (unsigned short)(b - 1) : (unsigned short)(b + 1);
}
__device__ __forceinline__ unsigned short hprev(unsigned short b) {
    if (b == 0x0000u) return 0x8001u;
    return (b & 0x8000u) ? (unsigned short)(b + 1) : (unsigned short)(b - 1);
}
__device__ __forceinline__ bool unsafe_val(float s) {
    __half h = __float2half_rn(s);
    unsigned short b = __half_as_ushort(h);
    float hv = __half2float(h);
    float up = __half2float(__ushort_as_half(hnext(b)));
    float dn = __half2float(__ushort_as_half(hprev(b)));
    return (0.5f * (hv + up) - s < T_FLAG) || (s - 0.5f * (hv + dn) < T_FLAG);
}

// ---------------------------------------------------------------------------
// FAST GEMM: f16 wmma, f32 accumulate (products exact; only sum order differs).
// Writes raw sums to g_sfast, provisional tv to out, fast pos, nz list.
// ---------------------------------------------------------------------------
#define BM 128
#define BN 128
#define BK 32
#define APAD 40

__global__ void gemm_fast_kernel(const float* __restrict__ x,
                                 const float* __restrict__ w,
                                 const float* __restrict__ bias,
                                 float* __restrict__ out) {
    extern __shared__ char smem[];
    __half* As = (__half*)smem;
    __half* Bs = (__half*)(smem + BM * APAD * 2);
    float*  Cs = (float*)smem;

    int tid  = threadIdx.x;
    int warp = tid >> 5;
    int wm   = warp >> 2;
    int wn   = warp & 3;
    int rowBase = blockIdx.y * BM;
    int colBase = blockIdx.x * BN;

    wmma::fragment<wmma::accumulator, 16, 16, 16, float> cfrag[4][2];
#pragma unroll
    for (int i = 0; i < 4; i++)
#pragma unroll
        for (int j = 0; j < 2; j++) wmma::fill_fragment(cfrag[i][j], 0.0f);

    for (int k0 = 0; k0 < DIN; k0 += BK) {
        __syncthreads();
#pragma unroll
        for (int l = tid; l < 1024; l += 256) {
            int r = l >> 3, c = (l & 7) * 4;
            float4 va = *(const float4*)(x + (size_t)(rowBase + r) * DIN + k0 + c);
            float4 vb = *(const float4*)(w + (size_t)(colBase + r) * DIN + k0 + c);
            uint2 pa, pb;
            ((__half2*)&pa)[0] = __floats2half2_rn(va.x, va.y);
            ((__half2*)&pa)[1] = __floats2half2_rn(va.z, va.w);
            ((__half2*)&pb)[0] = __floats2half2_rn(vb.x, vb.y);
            ((__half2*)&pb)[1] = __floats2half2_rn(vb.z, vb.w);
            *(uint2*)(As + r * APAD + c) = pa;
            *(uint2*)(Bs + r * APAD + c) = pb;
        }
        __syncthreads();
#pragma unroll
        for (int kk = 0; kk < BK; kk += 16) {
            wmma::fragment<wmma::matrix_a, 16, 16, 16, __half, wmma::row_major> afrag[4];
            wmma::fragment<wmma::matrix_b, 16, 16, 16, __half, wmma::col_major> bfrag[2];
#pragma unroll
            for (int i = 0; i < 4; i++)
                wmma::load_matrix_sync(afrag[i], As + (wm * 64 + i * 16) * APAD + kk, APAD);
#pragma unroll
            for (int j = 0; j < 2; j++)
                wmma::load_matrix_sync(bfrag[j], Bs + (wn * 32 + j * 16) * APAD + kk, APAD);
#pragma unroll
            for (int i = 0; i < 4; i++)
#pragma unroll
                for (int j = 0; j < 2; j++)
                    wmma::mma_sync(cfrag[i][j], afrag[i], bfrag[j], cfrag[i][j]);
        }
    }
    __syncthreads();
#pragma unroll
    for (int i = 0; i < 4; i++)
#pragma unroll
        for (int j = 0; j < 2; j++)
            wmma::store_matrix_sync(Cs + (wm * 64 + i * 16) * BN + wn * 32 + j * 16,
                                    cfrag[i][j], BN, wmma::mem_row_major);
    __syncthreads();

    int pos = 0;
#pragma unroll 4
    for (int e = 0; e < 64; e++) {
        int lin = tid + 256 * e;
        int r = lin >> 7, c = lin & 127;
        int row = rowBase + r, col = colBase + c;
        float acc = Cs[lin];
        g_sfast[(size_t)row * DOUT + col] = acc;
        __half hmm = __float2half(acc);
        float tvf = __half2float(hmm) + bias[col];
        __half h = __float2half(tvf);
        float hv = __half2float(h);
        out[OFF_TV + (size_t)row * DOUT + col] = hv;
        pos += (hv > 0.0f) ? 1 : 0;
        if (fabsf(hv) < NZ_TVMAX && unsafe_val(acc)) {
            int idx = atomicAdd(&g_nz_cnt, 1);
            if (idx < LIST_CAP) g_nz[idx] = make_int2(row, col);
        }
    }
#pragma unroll
    for (int off = 16; off; off >>= 1) pos += __shfl_down_sync(~0u, pos, off);
    __shared__ int spos[8];
    if ((tid & 31) == 0) spos[warp] = pos;
    __syncthreads();
    if (tid == 0) {
        int t = 0;
        for (int i = 0; i < 8; i++) t += spos[i];
        atomicAdd(&g_pos, t);
    }
}

// ---------------------------------------------------------------------------
// Exact-chain recompute of listed elements (one thread per element).
// Chain is bit-identical to the round-7 exact GEMM: ascending k, kc=320
// panels folded left-to-right, tail 256. which: 0 = nz list (update pos).
// ---------------------------------------------------------------------------
__global__ void recompute_list_kernel(const float* __restrict__ x,
                                      const float* __restrict__ w,
                                      const float* __restrict__ bias,
                                      float* __restrict__ out, int which) {
    int cnt = (which == 0) ? g_nz_cnt : g_bd_cnt;
    if (cnt > LIST_CAP) cnt = LIST_CAP;
    const int2* list = (which == 0) ? g_nz : g_bd;
    int posDelta = 0;

    for (int idx = blockIdx.x * blockDim.x + threadIdx.x; idx < cnt;
         idx += gridDim.x * blockDim.x) {
        int row = list[idx].x, col = list[idx].y;
        const float* xp = x + (size_t)row * DIN;
        const float* wp = w + (size_t)col * DIN;
        float accT = 0.0f;
        int k = 0;
#pragma unroll 1
        for (int t = 0; t < 13; t++) {
            int kend = (t < 12) ? (t + 1) * 320 : DIN;
            float accC = 0.0f;
#pragma unroll 1
            for (; k < kend; k += 16) {
                float4 a0 = *(const float4*)(xp + k);
                float4 b0 = *(const float4*)(wp + k);
                float4 a1 = *(const float4*)(xp + k + 4);
                float4 b1 = *(const float4*)(wp + k + 4);
                float4 a2 = *(const float4*)(xp + k + 8);
                float4 b2 = *(const float4*)(wp + k + 8);
                float4 a3 = *(const float4*)(xp + k + 12);
                float4 b3 = *(const float4*)(wp + k + 12);
                accC = __fmaf_rn(a0.x, b0.x, accC);
                accC = __fmaf_rn(a0.y, b0.y, accC);
                accC = __fmaf_rn(a0.z, b0.z, accC);
                accC = __fmaf_rn(a0.w, b0.w, accC);
                accC = __fmaf_rn(a1.x, b1.x, accC);
                accC = __fmaf_rn(a1.y, b1.y, accC);
                accC = __fmaf_rn(a1.z, b1.z, accC);
                accC = __fmaf_rn(a1.w, b1.w, accC);
                accC = __fmaf_rn(a2.x, b2.x, accC);
                accC = __fmaf_rn(a2.y, b2.y, accC);
                accC = __fmaf_rn(a2.z, b2.z, accC);
                accC = __fmaf_rn(a2.w, b2.w, accC);
                accC = __fmaf_rn(a3.x, b3.x, accC);
                accC = __fmaf_rn(a3.y, b3.y, accC);
                accC = __fmaf_rn(a3.z, b3.z, accC);
                accC = __fmaf_rn(a3.w, b3.w, accC);
            }
            accT = accT + accC;
        }
        __half hmm = __float2half(accT);
        float tvf = __half2float(hmm) + bias[col];
        __half h = __float2half(tvf);
        float hv = __half2float(h);
        size_t o = OFF_TV + (size_t)row * DOUT + col;
        float old = out[o];
        if (which == 0)
            posDelta += ((hv > 0.0f) ? 1 : 0) - ((old > 0.0f) ? 1 : 0);
        out[o] = hv;
    }
    if (which == 0) {
#pragma unroll
        for (int off = 16; off; off >>= 1)
            posDelta += __shfl_down_sync(~0u, posDelta, off);
        if ((threadIdx.x & 31) == 0 && posDelta != 0) atomicAdd(&g_pos, posDelta);
    }
}

// ---------------------------------------------------------------------------
__global__ void limit_kernel() {
    g_limit = (int)floorf((0.2f * (float)g_pos) / 2048.0f);
}

// ---------------------------------------------------------------------------
__device__ __forceinline__ unsigned key16f(float f) {
    unsigned short b = __half_as_ushort(__float2half(f));
    if (b == 0x8000u) b = 0;
    return (b & 0x8000u) ? (unsigned)(0xFFFFu ^ b) : (unsigned)(b | 0x8000u);
}

// ---------------------------------------------------------------------------
// Phase A: per row, find fast threshold K; collect flagged elements with
// key within +-BAND of K into g_bd. No counting here.
// ---------------------------------------------------------------------------
__global__ void topmask_find_kernel(const float* __restrict__ tv) {
    int row = blockIdx.x;
    int limit = g_limit;
    if (limit <= 0) return;

    __shared__ int hist[256];
    __shared__ int sB, sChi, sK;
    int tid = threadIdx.x;
    const float* tvr = tv + (size_t)row * DOUT;

    hist[tid] = 0;
    __syncthreads();
    for (int j = tid; j < DOUT; j += 256)
        atomicAdd(&hist[key16f(tvr[j]) >> 8], 1);
    __syncthreads();
    if (tid == 0) {
        int c = 0, b = 255;
        for (; b > 0; b--) {
            if (c + hist[b] >= limit) break;
            c += hist[b];
        }
        sB = b; sChi = c;
    }
    __syncthreads();
    int b = sB, chi = sChi;

    hist[tid] = 0;
    __syncthreads();
    for (int j = tid; j < DOUT; j += 256) {
        unsigned u = key16f(tvr[j]);
        if ((int)(u >> 8) == b) atomicAdd(&hist[u & 255], 1);
    }
    __syncthreads();
    if (tid == 0) {
        int c = chi, lb = 255;
        for (; lb > 0; lb--) {
            if (c + hist[lb] >= limit) break;
            c += hist[lb];
        }
        sK = (b << 8) | lb;
    }
    __syncthreads();
    int K = sK;

    for (int j = tid; j < DOUT; j += 256) {
        int key = (int)key16f(tvr[j]);
        if (key >= K - BAND && key <= K + BAND) {
            float s = g_sfast[(size_t)row * DOUT + j];
            if (unsafe_val(s)) {
                int idx = atomicAdd(&g_bd_cnt, 1);
                if (idx < LIST_CAP) g_bd[idx] = make_int2(row, j);
            }
        }
    }
}

// ---------------------------------------------------------------------------
// Phase B: exact per-row top-limit selection on corrected tv; counts += mask.
// ---------------------------------------------------------------------------
__global__ void topmask_kernel(const float* __restrict__ tv) {
    int row = blockIdx.x;
    int limit = g_limit;
    if (limit <= 0) return;

    __shared__ int hist[256];
    __shared__ int scan[256];
    __shared__ int sB, sChi, sK, sNeed;
    int tid = threadIdx.x;
    const float* tvr = tv + (size_t)row * DOUT;

    hist[tid] = 0;
    __syncthreads();
    for (int j = tid; j < DOUT; j += 256)
        atomicAdd(&hist[key16f(tvr[j]) >> 8], 1);
    __syncthreads();
    if (tid == 0) {
        int c = 0, b = 255;
        for (; b > 0; b--) {
            if (c + hist[b] >= limit) break;
            c += hist[b];
        }
        sB = b; sChi = c;
    }
    __syncthreads();
    int b = sB, chi = sChi;

    hist[tid] = 0;
    __syncthreads();
    for (int j = tid; j < DOUT; j += 256) {
        unsigned u = key16f(tvr[j]);
        if ((int)(u >> 8) == b) atomicAdd(&hist[u & 255], 1);
    }
    __syncthreads();
    if (tid == 0) {
        int c = chi, lb = 255;
        for (; lb > 0; lb--) {
            if (c + hist[lb] >= limit) break;
            c += hist[lb];
        }
        sK = (b << 8) | lb;
        sNeed = limit - c;
    }
    __syncthreads();
    unsigned K = (unsigned)sK;
    int need = sNeed;

    int j0 = tid * 43;
    int myTies = 0;
    for (int j = j0; j < j0 + 43; j++) {
        unsigned u = key16f(tvr[j]);
        if (u > K) atomicAdd(&g_counts[j], 1);
        else if (u == K) myTies++;
    }
    scan[tid] = myTies;
    __syncthreads();
    for (int off = 1; off < 256; off <<= 1) {
        int t = (tid >= off) ? scan[tid - off] : 0;
        __syncthreads();
        scan[tid] += t;
        __syncthreads();
    }
    int rank = scan[tid] - myTies;
    if (myTies > 0) {
        for (int j = j0; j < j0 + 43; j++) {
            if (key16f(tvr[j]) == K) {
                if (rank < need) atomicAdd(&g_counts[j], 1);
                rank++;
            }
        }
    }
}

// ---------------------------------------------------------------------------
__global__ void sort_kernel(const float* __restrict__ bias, float* __restrict__ out) {
    extern __shared__ unsigned keys[];
    int tid = threadIdx.x;
    for (int i = tid; i < 16384; i += 1024) {
        int cnt = (i < DOUT) ? g_counts[i] : 0;
        keys[i] = ((unsigned)cnt << 14) | (unsigned)(16383 - i);
    }
    __syncthreads();
    for (unsigned k = 2; k <= 16384; k <<= 1) {
        for (unsigned j = k >> 1; j > 0; j >>= 1) {
            for (int i = tid; i < 16384; i += 1024) {
                unsigned ixj = (unsigned)i ^ j;
                if (ixj > (unsigned)i) {
                    unsigned a = keys[i], c = keys[ixj];
                    bool desc = ((i & k) == 0);
                    if (desc ? (a < c) : (a > c)) { keys[i] = c; keys[ixj] = a; }
                }
            }
            __syncthreads();
        }
    }
    for (int i = tid; i < REMAINED; i += 1024) {
        int idx = 16383 - (int)(keys[i] & 16383u);
        g_indices[i] = idx;
        out[OFF_BIAS + i] = bias[idx];
        out[OFF_IDX + i]  = (float)idx;
    }
}

// ---------------------------------------------------------------------------
__global__ void gather_kernel(const float* __restrict__ w, float* __restrict__ out) {
    int i = blockIdx.x * blockDim.x + threadIdx.x;
    const int total8 = REMAINED * (DIN / 8);
    if (i >= total8) return;
    int r = i / (DIN / 8);
    int c8 = i % (DIN / 8);
    int src = g_indices[r];
    const float* s = w + (size_t)src * DIN + (size_t)c8 * 8;
    float* o = out + OFF_W + (size_t)r * DIN + (size_t)c8 * 8;
    float4 v0 = *(const float4*)(s);
    float4 v1 = *(const float4*)(s + 4);
    *(float4*)(o)     = v0;
    *(float4*)(o + 4) = v1;
}

// ---------------------------------------------------------------------------
extern "C" void kernel_launch(void* const* d_in, const int* in_sizes, int n_in,
                              void* d_out, int out_size) {
    const float* x    = (const float*)d_in[0];
    const float* w    = (const float*)d_in[1];
    const float* bias = (const float*)d_in[2];
    float* out = (float*)d_out;

    cudaFuncSetAttribute(gemm_fast_kernel, cudaFuncAttributeMaxDynamicSharedMemorySize, 65536);
    cudaFuncSetAttribute(sort_kernel, cudaFuncAttributeMaxDynamicSharedMemorySize, 65536);

    init_kernel<<<(DOUT + 255) / 256, 256>>>();
    gemm_fast_kernel<<<dim3(DOUT / BN, S_DIM / BM), 256, 65536>>>(x, w, bias, out);
    recompute_list_kernel<<<256, 256>>>(x, w, bias, out, 0);   // near-zero: fix pos
    limit_kernel<<<1, 1>>>();
    topmask_find_kernel<<<S_DIM, 256>>>(out + OFF_TV);         // per-row K + band list
    recompute_list_kernel<<<256, 256>>>(x, w, bias, out, 1);   // boundary: fix keys
    topmask_kernel<<<S_DIM, 256>>>(out + OFF_TV);              // exact counts
    sort_kernel<<<1, 1024, 65536>>>(bias, out);
    gather_kernel<<<(REMAINED * (DIN / 8) + 255) / 256, 256>>>(w, out);
}

// round 12
// speedup vs baseline: 4.6248x; 1.6134x over previous
#include <cuda_runtime.h>
#include <cuda_fp16.h>
#include <mma.h>
#include <cstdint>
#include <cstddef>

using namespace nvcuda;

#define S_DIM 2048
#define DIN 4096
#define DOUT 11008
#define REMAINED 3852

#define T_FLAG 1.5e-6f
#define NZ_TVMAX 1e-4f
#define BAND 3
#define LIST_CAP 131072

// Output layout (float32 concat): tv | filtered_W | filtered_bias | indices
#define OFF_TV   ((size_t)0)
#define N_TV     ((size_t)S_DIM * DOUT)
#define OFF_W    (N_TV)
#define N_W      ((size_t)REMAINED * DIN)
#define OFF_BIAS (OFF_W + N_W)
#define OFF_IDX  (OFF_BIAS + REMAINED)

// Scratch (device globals — no allocation allowed)
__device__ int g_counts[DOUT];
__device__ int g_pos;
__device__ int g_limit;
__device__ int g_indices[REMAINED];
__device__ float g_sfast[(size_t)S_DIM * DOUT];
__device__ __half g_xh[(size_t)S_DIM * DIN];
__device__ __half g_wh[(size_t)DOUT * DIN];
__device__ int  g_nz_cnt;
__device__ int2 g_nz[LIST_CAP];
__device__ int  g_bd_cnt;
__device__ int2 g_bd[LIST_CAP];

// ---------------------------------------------------------------------------
__global__ void init_kernel() {
    int i = blockIdx.x * blockDim.x + threadIdx.x;
    if (i < DOUT) g_counts[i] = 0;
    if (i == 0) { g_pos = 0; g_nz_cnt = 0; g_bd_cnt = 0; }
}

// ---------------------------------------------------------------------------
// Exact f32 -> f16 pre-conversion (values are f16 images). 8 elems/thread.
// ---------------------------------------------------------------------------
__global__ void convert_kernel(const float* __restrict__ src,
                               __half* __restrict__ dst, int n8) {
    int i = blockIdx.x * blockDim.x + threadIdx.x;
    if (i >= n8) return;
    float4 v0 = *((const float4*)src + i * 2);
    float4 v1 = *((const float4*)src + i * 2 + 1);
    uint4 p;
    ((__half2*)&p)[0] = __floats2half2_rn(v0.x, v0.y);
    ((__half2*)&p)[1] = __floats2half2_rn(v0.z, v0.w);
    ((__half2*)&p)[2] = __floats2half2_rn(v1.x, v1.y);
    ((__half2*)&p)[3] = __floats2half2_rn(v1.z, v1.w);
    *((uint4*)dst + i) = p;
}

// ---------------------------------------------------------------------------
// FAST GEMM: f16 wmma, f32 acc, cp.async double-buffered, 128x256 tile.
// Per-element k-order identical to round 10 (ascending 16-chunks) -> g_sfast
// bit-identical. Raw sums stored straight to g_sfast.
// ---------------------------------------------------------------------------
#define GBM 128
#define GBN 256
#define GBK 32
#define PAD 40   // halves per smem row (80B, 16B-aligned)

__device__ __forceinline__ void cp16(void* dst, const void* src) {
    unsigned ds = (unsigned)__cvta_generic_to_shared(dst);
    asm volatile("cp.async.cg.shared.global [%0], [%1], 16;"
                 :: "r"(ds), "l"(src));
}

__global__ void __launch_bounds__(256) gemm_fast_kernel(float* __restrict__ gs) {
    extern __shared__ char smem[];
    __half* As = (__half*)smem;                          // [2][128*PAD]
    __half* Bs = (__half*)(smem + 2 * GBM * PAD * 2);    // [2][256*PAD]

    int tid  = threadIdx.x;
    int warp = tid >> 5;
    int wm   = warp >> 2;       // 0..1 -> 64-row slab
    int wn   = warp & 3;        // 0..3 -> 64-col slab
    int rowBase = blockIdx.y * GBM;
    int colBase = blockIdx.x * GBN;

    wmma::fragment<wmma::accumulator, 16, 16, 16, float> acc[4][4];
#pragma unroll
    for (int i = 0; i < 4; i++)
#pragma unroll
        for (int j = 0; j < 4; j++) wmma::fill_fragment(acc[i][j], 0.0f);

    int ra = tid >> 2, qa = tid & 3;   // A: 128 rows x 4 chunks, 2 passes

    // prologue: async-load chunk 0
    {
        const __half* xa = g_xh + (size_t)rowBase * DIN;
        const __half* wb = g_wh + (size_t)colBase * DIN;
#pragma unroll
        for (int p = 0; p < 2; p++) {
            int idx = tid + p * 256;
            int r = idx >> 2, q = idx & 3;
            cp16(&As[r * PAD + q * 8], xa + (size_t)r * DIN + q * 8);
        }
#pragma unroll
        for (int p = 0; p < 4; p++) {
            int idx = tid + p * 256;
            int r = idx >> 2, q = idx & 3;
            cp16(&Bs[r * PAD + q * 8], wb + (size_t)r * DIN + q * 8);
        }
        asm volatile("cp.async.commit_group;");
    }

    for (int c = 0; c < DIN / GBK; c++) {
        int buf = c & 1;
        asm volatile("cp.async.wait_group 0;");
        __syncthreads();
        if (c + 1 < DIN / GBK) {
            int nb = (c + 1) & 1;
            int k0 = (c + 1) * GBK;
            const __half* xa = g_xh + (size_t)rowBase * DIN + k0;
            const __half* wb = g_wh + (size_t)colBase * DIN + k0;
#pragma unroll
            for (int p = 0; p < 2; p++) {
                int idx = tid + p * 256;
                int r = idx >> 2, q = idx & 3;
                cp16(&As[nb * GBM * PAD + r * PAD + q * 8], xa + (size_t)r * DIN + q * 8);
            }
#pragma unroll
            for (int p = 0; p < 4; p++) {
                int idx = tid + p * 256;
                int r = idx >> 2, q = idx & 3;
                cp16(&Bs[nb * GBN * PAD + r * PAD + q * 8], wb + (size_t)r * DIN + q * 8);
            }
            asm volatile("cp.async.commit_group;");
        }
        const __half* Ab = As + buf * GBM * PAD;
        const __half* Bb = Bs + buf * GBN * PAD;
#pragma unroll
        for (int kk = 0; kk < GBK; kk += 16) {
            wmma::fragment<wmma::matrix_a, 16, 16, 16, __half, wmma::row_major> af[4];
            wmma::fragment<wmma::matrix_b, 16, 16, 16, __half, wmma::col_major> bf[4];
#pragma unroll
            for (int i = 0; i < 4; i++)
                wmma::load_matrix_sync(af[i], Ab + (wm * 64 + i * 16) * PAD + kk, PAD);
#pragma unroll
            for (int j = 0; j < 4; j++)
                wmma::load_matrix_sync(bf[j], Bb + (wn * 64 + j * 16) * PAD + kk, PAD);
#pragma unroll
            for (int i = 0; i < 4; i++)
#pragma unroll
                for (int j = 0; j < 4; j++)
                    wmma::mma_sync(acc[i][j], af[i], bf[j], acc[i][j]);
        }
    }

    // store raw sums directly to g_sfast
#pragma unroll
    for (int i = 0; i < 4; i++)
#pragma unroll
        for (int j = 0; j < 4; j++) {
            int row = rowBase + wm * 64 + i * 16;
            int col = colBase + wn * 64 + j * 16;
            wmma::store_matrix_sync(gs + (size_t)row * DOUT + col, acc[i][j],
                                    DOUT, wmma::mem_row_major);
        }
}

// ---------------------------------------------------------------------------
// Flag test (validated round 9/10)
// ---------------------------------------------------------------------------
__device__ __forceinline__ unsigned short hnext(unsigned short b) {
    if (b == 0x8000u) return 0x0001u;
    return (b & 0x8000u) ? (unsigned short)(b - 1) : (unsigned short)(b + 1);
}
__device__ __forceinline__ unsigned short hprev(unsigned short b) {
    if (b == 0x0000u) return 0x8001u;
    return (b & 0x8000u) ? (unsigned short)(b + 1) : (unsigned short)(b - 1);
}
__device__ __forceinline__ bool unsafe_val(float s) {
    __half h = __float2half_rn(s);
    unsigned short b = __half_as_ushort(h);
    float hv = __half2float(h);
    float up = __half2float(__ushort_as_half(hnext(b)));
    float dn = __half2float(__ushort_as_half(hprev(b)));
    return (0.5f * (hv + up) - s < T_FLAG) || (s - 0.5f * (hv + dn) < T_FLAG);
}

// ---------------------------------------------------------------------------
// Epilogue: read g_sfast, write tv, count pos, collect nz list. float4 lanes.
// ---------------------------------------------------------------------------
__global__ void epilogue_kernel(const float* __restrict__ bias,
                                float* __restrict__ out) {
    int i = blockIdx.x * blockDim.x + threadIdx.x;   // one float4
    const int total4 = (int)(N_TV / 4);
    int pos = 0;
    if (i < total4) {
        int row = i / (DOUT / 4);
        int c4  = i - row * (DOUT / 4);
        float4 s = *((const float4*)(g_sfast + (size_t)row * DOUT) + c4);
        float4 b = *((const float4*)bias + c4);
        float sv[4] = {s.x, s.y, s.z, s.w};
        float bv[4] = {b.x, b.y, b.z, b.w};
        float tv[4];
#pragma unroll
        for (int e = 0; e < 4; e++) {
            __half hmm = __float2half(sv[e]);
            float tvf = __half2float(hmm) + bv[e];
            __half h = __float2half(tvf);
            tv[e] = __half2float(h);
            pos += (tv[e] > 0.0f) ? 1 : 0;
            if (fabsf(tv[e]) < NZ_TVMAX && unsafe_val(sv[e])) {
                int idx = atomicAdd(&g_nz_cnt, 1);
                if (idx < LIST_CAP) g_nz[idx] = make_int2(row, c4 * 4 + e);
            }
        }
        *((float4*)(out + OFF_TV + (size_t)row * DOUT) + c4) =
            make_float4(tv[0], tv[1], tv[2], tv[3]);
    }
#pragma unroll
    for (int off = 16; off; off >>= 1) pos += __shfl_down_sync(~0u, pos, off);
    __shared__ int spos[8];
    if ((threadIdx.x & 31) == 0) spos[threadIdx.x >> 5] = pos;
    __syncthreads();
    if (threadIdx.x == 0) {
        int t = 0;
        for (int k = 0; k < 8; k++) t += spos[k];
        if (t) atomicAdd(&g_pos, t);
    }
}

// ---------------------------------------------------------------------------
// Exact-chain recompute of listed elements (round-7-bit-identical chain).
// ---------------------------------------------------------------------------
__global__ void recompute_list_kernel(const float* __restrict__ x,
                                      const float* __restrict__ w,
                                      const float* __restrict__ bias,
                                      float* __restrict__ out, int which) {
    int cnt = (which == 0) ? g_nz_cnt : g_bd_cnt;
    if (cnt > LIST_CAP) cnt = LIST_CAP;
    const int2* list = (which == 0) ? g_nz : g_bd;
    int posDelta = 0;

    for (int idx = blockIdx.x * blockDim.x + threadIdx.x; idx < cnt;
         idx += gridDim.x * blockDim.x) {
        int row = list[idx].x, col = list[idx].y;
        const float* xp = x + (size_t)row * DIN;
        const float* wp = w + (size_t)col * DIN;
        float accT = 0.0f;
        int k = 0;
#pragma unroll 1
        for (int t = 0; t < 13; t++) {
            int kend = (t < 12) ? (t + 1) * 320 : DIN;
            float accC = 0.0f;
#pragma unroll 1
            for (; k < kend; k += 16) {
                float4 a0 = *(const float4*)(xp + k);
                float4 b0 = *(const float4*)(wp + k);
                float4 a1 = *(const float4*)(xp + k + 4);
                float4 b1 = *(const float4*)(wp + k + 4);
                float4 a2 = *(const float4*)(xp + k + 8);
                float4 b2 = *(const float4*)(wp + k + 8);
                float4 a3 = *(const float4*)(xp + k + 12);
                float4 b3 = *(const float4*)(wp + k + 12);
                accC = __fmaf_rn(a0.x, b0.x, accC);
                accC = __fmaf_rn(a0.y, b0.y, accC);
                accC = __fmaf_rn(a0.z, b0.z, accC);
                accC = __fmaf_rn(a0.w, b0.w, accC);
                accC = __fmaf_rn(a1.x, b1.x, accC);
                accC = __fmaf_rn(a1.y, b1.y, accC);
                accC = __fmaf_rn(a1.z, b1.z, accC);
                accC = __fmaf_rn(a1.w, b1.w, accC);
                accC = __fmaf_rn(a2.x, b2.x, accC);
                accC = __fmaf_rn(a2.y, b2.y, accC);
                accC = __fmaf_rn(a2.z, b2.z, accC);
                accC = __fmaf_rn(a2.w, b2.w, accC);
                accC = __fmaf_rn(a3.x, b3.x, accC);
                accC = __fmaf_rn(a3.y, b3.y, accC);
                accC = __fmaf_rn(a3.z, b3.z, accC);
                accC = __fmaf_rn(a3.w, b3.w, accC);
            }
            accT = accT + accC;
        }
        __half hmm = __float2half(accT);
        float tvf = __half2float(hmm) + bias[col];
        __half h = __float2half(tvf);
        float hv = __half2float(h);
        size_t o = OFF_TV + (size_t)row * DOUT + col;
        float old = out[o];
        if (which == 0)
            posDelta += ((hv > 0.0f) ? 1 : 0) - ((old > 0.0f) ? 1 : 0);
        out[o] = hv;
    }
    if (which == 0) {
#pragma unroll
        for (int off = 16; off; off >>= 1)
            posDelta += __shfl_down_sync(~0u, posDelta, off);
        if ((threadIdx.x & 31) == 0 && posDelta != 0) atomicAdd(&g_pos, posDelta);
    }
}

// ---------------------------------------------------------------------------
__global__ void limit_kernel() {
    g_limit = (int)floorf((0.2f * (float)g_pos) / 2048.0f);
}

// ---------------------------------------------------------------------------
__device__ __forceinline__ unsigned key16f(float f) {
    unsigned short b = __half_as_ushort(__float2half(f));
    if (b == 0x8000u) b = 0;
    return (b & 0x8000u) ? (unsigned)(0xFFFFu ^ b) : (unsigned)(b | 0x8000u);
}

// ---------------------------------------------------------------------------
// Phase A: per row, fast threshold K; collect flagged band elements.
// ---------------------------------------------------------------------------
__global__ void topmask_find_kernel(const float* __restrict__ tv) {
    int row = blockIdx.x;
    int limit = g_limit;
    if (limit <= 0) return;

    __shared__ int hist[256];
    __shared__ int sB, sChi, sK;
    int tid = threadIdx.x;
    const float* tvr = tv + (size_t)row * DOUT;

    hist[tid] = 0;
    __syncthreads();
    for (int j = tid; j < DOUT; j += 256)
        atomicAdd(&hist[key16f(tvr[j]) >> 8], 1);
    __syncthreads();
    if (tid == 0) {
        int c = 0, b = 255;
        for (; b > 0; b--) {
            if (c + hist[b] >= limit) break;
            c += hist[b];
        }
        sB = b; sChi = c;
    }
    __syncthreads();
    int b = sB, chi = sChi;

    hist[tid] = 0;
    __syncthreads();
    for (int j = tid; j < DOUT; j += 256) {
        unsigned u = key16f(tvr[j]);
        if ((int)(u >> 8) == b) atomicAdd(&hist[u & 255], 1);
    }
    __syncthreads();
    if (tid == 0) {
        int c = chi, lb = 255;
        for (; lb > 0; lb--) {
            if (c + hist[lb] >= limit) break;
            c += hist[lb];
        }
        sK = (b << 8) | lb;
    }
    __syncthreads();
    int K = sK;

    for (int j = tid; j < DOUT; j += 256) {
        int key = (int)key16f(tvr[j]);
        if (key >= K - BAND && key <= K + BAND) {
            float s = g_sfast[(size_t)row * DOUT + j];
            if (unsafe_val(s)) {
                int idx = atomicAdd(&g_bd_cnt, 1);
                if (idx < LIST_CAP) g_bd[idx] = make_int2(row, j);
            }
        }
    }
}

// ---------------------------------------------------------------------------
// Phase B: exact per-row top-limit selection; counts += mask.
// ---------------------------------------------------------------------------
__global__ void topmask_kernel(const float* __restrict__ tv) {
    int row = blockIdx.x;
    int limit = g_limit;
    if (limit <= 0) return;

    __shared__ int hist[256];
    __shared__ int scan[256];
    __shared__ int sB, sChi, sK, sNeed;
    int tid = threadIdx.x;
    const float* tvr = tv + (size_t)row * DOUT;

    hist[tid] = 0;
    __syncthreads();
    for (int j = tid; j < DOUT; j += 256)
        atomicAdd(&hist[key16f(tvr[j]) >> 8], 1);
    __syncthreads();
    if (tid == 0) {
        int c = 0, b = 255;
        for (; b > 0; b--) {
            if (c + hist[b] >= limit) break;
            c += hist[b];
        }
        sB = b; sChi = c;
    }
    __syncthreads();
    int b = sB, chi = sChi;

    hist[tid] = 0;
    __syncthreads();
    for (int j = tid; j < DOUT; j += 256) {
        unsigned u = key16f(tvr[j]);
        if ((int)(u >> 8) == b) atomicAdd(&hist[u & 255], 1);
    }
    __syncthreads();
    if (tid == 0) {
        int c = chi, lb = 255;
        for (; lb > 0; lb--) {
            if (c + hist[lb] >= limit) break;
            c += hist[lb];
        }
        sK = (b << 8) | lb;
        sNeed = limit - c;
    }
    __syncthreads();
    unsigned K = (unsigned)sK;
    int need = sNeed;

    int j0 = tid * 43;
    int myTies = 0;
    for (int j = j0; j < j0 + 43; j++) {
        unsigned u = key16f(tvr[j]);
        if (u > K) atomicAdd(&g_counts[j], 1);
        else if (u == K) myTies++;
    }
    scan[tid] = myTies;
    __syncthreads();
    for (int off = 1; off < 256; off <<= 1) {
        int t = (tid >= off) ? scan[tid - off] : 0;
        __syncthreads();
        scan[tid] += t;
        __syncthreads();
    }
    int rank = scan[tid] - myTies;
    if (myTies > 0) {
        for (int j = j0; j < j0 + 43; j++) {
            if (key16f(tvr[j]) == K) {
                if (rank < need) atomicAdd(&g_counts[j], 1);
                rank++;
            }
        }
    }
}

// ---------------------------------------------------------------------------
__global__ void sort_kernel(const float* __restrict__ bias, float* __restrict__ out) {
    extern __shared__ unsigned keys[];
    int tid = threadIdx.x;
    for (int i = tid; i < 16384; i += 1024) {
        int cnt = (i < DOUT) ? g_counts[i] : 0;
        keys[i] = ((unsigned)cnt << 14) | (unsigned)(16383 - i);
    }
    __syncthreads();
    for (unsigned k = 2; k <= 16384; k <<= 1) {
        for (unsigned j = k >> 1; j > 0; j >>= 1) {
            for (int i = tid; i < 16384; i += 1024) {
                unsigned ixj = (unsigned)i ^ j;
                if (ixj > (unsigned)i) {
                    unsigned a = keys[i], c = keys[ixj];
                    bool desc = ((i & k) == 0);
                    if (desc ? (a < c) : (a > c)) { keys[i] = c; keys[ixj] = a; }
                }
            }
            __syncthreads();
        }
    }
    for (int i = tid; i < REMAINED; i += 1024) {
        int idx = 16383 - (int)(keys[i] & 16383u);
        g_indices[i] = idx;
        out[OFF_BIAS + i] = bias[idx];
        out[OFF_IDX + i]  = (float)idx;
    }
}

// ---------------------------------------------------------------------------
__global__ void gather_kernel(const float* __restrict__ w, float* __restrict__ out) {
    int i = blockIdx.x * blockDim.x + threadIdx.x;
    const int total8 = REMAINED * (DIN / 8);
    if (i >= total8) return;
    int r = i / (DIN / 8);
    int c8 = i % (DIN / 8);
    int src = g_indices[r];
    const float* s = w + (size_t)src * DIN + (size_t)c8 * 8;
    float* o = out + OFF_W + (size_t)r * DIN + (size_t)c8 * 8;
    float4 v0 = *(const float4*)(s);
    float4 v1 = *(const float4*)(s + 4);
    *(float4*)(o)     = v0;
    *(float4*)(o + 4) = v1;
}

// ---------------------------------------------------------------------------
extern "C" void kernel_launch(void* const* d_in, const int* in_sizes, int n_in,
                              void* d_out, int out_size) {
    const float* x    = (const float*)d_in[0];
    const float* w    = (const float*)d_in[1];
    const float* bias = (const float*)d_in[2];
    float* out = (float*)d_out;

    static __half* xh_p = nullptr;
    static __half* wh_p = nullptr;
    static float* sfast_p = nullptr;
    if (!xh_p) {
        cudaGetSymbolAddress((void**)&xh_p, g_xh);
        cudaGetSymbolAddress((void**)&wh_p, g_wh);
        cudaGetSymbolAddress((void**)&sfast_p, g_sfast);
    }

    const int GEMM_SMEM = 2 * (GBM + GBN) * PAD * 2;  // 61440 B
    cudaFuncSetAttribute(gemm_fast_kernel, cudaFuncAttributeMaxDynamicSharedMemorySize, GEMM_SMEM);
    cudaFuncSetAttribute(sort_kernel, cudaFuncAttributeMaxDynamicSharedMemorySize, 65536);

    init_kernel<<<(DOUT + 255) / 256, 256>>>();
    convert_kernel<<<(S_DIM * DIN / 8 + 255) / 256, 256>>>(x, xh_p, S_DIM * DIN / 8);
    convert_kernel<<<(DOUT * DIN / 8 + 255) / 256, 256>>>(w, wh_p, DOUT * DIN / 8);
    gemm_fast_kernel<<<dim3(DOUT / GBN, S_DIM / GBM), 256, GEMM_SMEM>>>(sfast_p);
    epilogue_kernel<<<(int)((N_TV / 4 + 255) / 256), 256>>>(bias, out);
    recompute_list_kernel<<<256, 256>>>(x, w, bias, out, 0);
    limit_kernel<<<1, 1>>>();
    topmask_find_kernel<<<S_DIM, 256>>>(out + OFF_TV);
    recompute_list_kernel<<<256, 256>>>(x, w, bias, out, 1);
    topmask_kernel<<<S_DIM, 256>>>(out + OFF_TV);
    sort_kernel<<<1, 1024, 65536>>>(bias, out);
    gather_kernel<<<(REMAINED * (DIN / 8) + 255) / 256, 256>>>(w, out);
}

// round 15
// speedup vs baseline: 6.3651x; 1.3763x over previous
#include <cuda_runtime.h>
#include <cuda_fp16.h>
#include <mma.h>
#include <cstdint>
#include <cstddef>

using namespace nvcuda;

#define S_DIM 2048
#define DIN 4096
#define DOUT 11008
#define REMAINED 3852

#define T_FLAG 1.5e-6f
#define NZ_TVMAX 4e-6f
#define BAND 3
#define LIST_CAP 131072

// Output layout (float32 concat): tv | filtered_W | filtered_bias | indices
#define OFF_TV   ((size_t)0)
#define N_TV     ((size_t)S_DIM * DOUT)
#define OFF_W    (N_TV)
#define N_W      ((size_t)REMAINED * DIN)
#define OFF_BIAS (OFF_W + N_W)
#define OFF_IDX  (OFF_BIAS + REMAINED)

// Scratch (device globals — no allocation allowed)
__device__ int g_counts[DOUT];
__device__ int g_pos;
__device__ int g_limit;
__device__ int g_indices[REMAINED];
__device__ float g_sfast[(size_t)S_DIM * DOUT];
__device__ __half g_xh[(size_t)S_DIM * DIN];
__device__ __half g_wh[(size_t)DOUT * DIN];
__device__ unsigned short g_key[(size_t)S_DIM * DOUT];
__device__ int  g_nz_cnt;
__device__ int2 g_nz[LIST_CAP];
__device__ int  g_bd_cnt;
__device__ int2 g_bd[LIST_CAP];

// ---------------------------------------------------------------------------
__global__ void init_kernel() {
    int i = blockIdx.x * blockDim.x + threadIdx.x;
    if (i < DOUT) g_counts[i] = 0;
    if (i == 0) { g_pos = 0; g_nz_cnt = 0; g_bd_cnt = 0; }
}

// ---------------------------------------------------------------------------
// Exact f32 -> f16 pre-conversion (values are f16 images). 8 elems/thread.
// ---------------------------------------------------------------------------
__global__ void convert_kernel(const float* __restrict__ src,
                               __half* __restrict__ dst, int n8) {
    int i = blockIdx.x * blockDim.x + threadIdx.x;
    if (i >= n8) return;
    float4 v0 = *((const float4*)src + i * 2);
    float4 v1 = *((const float4*)src + i * 2 + 1);
    uint4 p;
    ((__half2*)&p)[0] = __floats2half2_rn(v0.x, v0.y);
    ((__half2*)&p)[1] = __floats2half2_rn(v0.z, v0.w);
    ((__half2*)&p)[2] = __floats2half2_rn(v1.x, v1.y);
    ((__half2*)&p)[3] = __floats2half2_rn(v1.z, v1.w);
    *((uint4*)dst + i) = p;
}

// ---------------------------------------------------------------------------
// FAST GEMM: f16 wmma, f32 acc, cp.async 2-stage, 128x256 tile, GBK=64.
// Per-element k-order unchanged (ascending 16-chunks) -> g_sfast bit-identical.
// ---------------------------------------------------------------------------
#define GBM 128
#define GBN 256
#define GBK 64
#define PAD 72   // halves per smem row (144B: ldmatrix rows conflict-free)

__device__ __forceinline__ void cp16(void* dst, const void* src) {
    unsigned ds = (unsigned)__cvta_generic_to_shared(dst);
    asm volatile("cp.async.cg.shared.global [%0], [%1], 16;"
                 :: "r"(ds), "l"(src));
}

__global__ void __launch_bounds__(256) gemm_fast_kernel(float* __restrict__ gs) {
    extern __shared__ char smem[];
    __half* As = (__half*)smem;                          // [2][128*PAD]
    __half* Bs = (__half*)(smem + 2 * GBM * PAD * 2);    // [2][256*PAD]

    int tid  = threadIdx.x;
    int warp = tid >> 5;
    int wm   = warp >> 2;
    int wn   = warp & 3;
    int rowBase = blockIdx.y * GBM;
    int colBase = blockIdx.x * GBN;

    wmma::fragment<wmma::accumulator, 16, 16, 16, float> acc[4][4];
#pragma unroll
    for (int i = 0; i < 4; i++)
#pragma unroll
        for (int j = 0; j < 4; j++) wmma::fill_fragment(acc[i][j], 0.0f);

    // stage loader: A 128x64 halves (4 cp/thread), B 256x64 (8 cp/thread)
    auto loadStage = [&](int st, int k0) {
        const __half* xa = g_xh + (size_t)rowBase * DIN + k0;
        const __half* wb = g_wh + (size_t)colBase * DIN + k0;
#pragma unroll
        for (int p = 0; p < 4; p++) {
            int idx = tid + p * 256;
            int r = idx >> 3, q = idx & 7;
            cp16(&As[st * GBM * PAD + r * PAD + q * 8], xa + (size_t)r * DIN + q * 8);
        }
#pragma unroll
        for (int p = 0; p < 8; p++) {
            int idx = tid + p * 256;
            int r = idx >> 3, q = idx & 7;
            cp16(&Bs[st * GBN * PAD + r * PAD + q * 8], wb + (size_t)r * DIN + q * 8);
        }
        asm volatile("cp.async.commit_group;");
    };

    loadStage(0, 0);

    const int NSTEP = DIN / GBK;   // 64
    for (int c = 0; c < NSTEP; c++) {
        int buf = c & 1;
        asm volatile("cp.async.wait_group 0;");
        __syncthreads();
        if (c + 1 < NSTEP) loadStage((c + 1) & 1, (c + 1) * GBK);
        const __half* Ab = As + buf * GBM * PAD;
        const __half* Bb = Bs + buf * GBN * PAD;
#pragma unroll
        for (int kk = 0; kk < GBK; kk += 16) {
            wmma::fragment<wmma::matrix_a, 16, 16, 16, __half, wmma::row_major> af[4];
            wmma::fragment<wmma::matrix_b, 16, 16, 16, __half, wmma::col_major> bf[4];
#pragma unroll
            for (int i = 0; i < 4; i++)
                wmma::load_matrix_sync(af[i], Ab + (wm * 64 + i * 16) * PAD + kk, PAD);
#pragma unroll
            for (int j = 0; j < 4; j++)
                wmma::load_matrix_sync(bf[j], Bb + (wn * 64 + j * 16) * PAD + kk, PAD);
#pragma unroll
            for (int i = 0; i < 4; i++)
#pragma unroll
                for (int j = 0; j < 4; j++)
                    wmma::mma_sync(acc[i][j], af[i], bf[j], acc[i][j]);
        }
        __syncthreads();
    }

#pragma unroll
    for (int i = 0; i < 4; i++)
#pragma unroll
        for (int j = 0; j < 4; j++) {
            int row = rowBase + wm * 64 + i * 16;
            int col = colBase + wn * 64 + j * 16;
            wmma::store_matrix_sync(gs + (size_t)row * DOUT + col, acc[i][j],
                                    DOUT, wmma::mem_row_major);
        }
}

// ---------------------------------------------------------------------------
// Flag test (validated round 9/10)
// ---------------------------------------------------------------------------
__device__ __forceinline__ unsigned short hnext(unsigned short b) {
    if (b == 0x8000u) return 0x0001u;
    return (b & 0x8000u) ? (unsigned short)(b - 1) : (unsigned short)(b + 1);
}
__device__ __forceinline__ unsigned short hprev(unsigned short b) {
    if (b == 0x0000u) return 0x8001u;
    return (b & 0x8000u) ? (unsigned short)(b + 1) : (unsigned short)(b - 1);
}
__device__ __forceinline__ bool unsafe_val(float s) {
    __half h = __float2half_rn(s);
    unsigned short b = __half_as_ushort(h);
    float hv = __half2float(h);
    float up = __half2float(__ushort_as_half(hnext(b)));
    float dn = __half2float(__ushort_as_half(hprev(b)));
    return (0.5f * (hv + up) - s < T_FLAG) || (s - 0.5f * (hv + dn) < T_FLAG);
}

__device__ __forceinline__ unsigned key16f(float f) {
    unsigned short b = __half_as_ushort(__float2half(f));
    if (b == 0x8000u) b = 0;
    return (b & 0x8000u) ? (unsigned)(0xFFFFu ^ b) : (unsigned)(b | 0x8000u);
}

// ---------------------------------------------------------------------------
// Epilogue: read g_sfast, write tv + u16 key image, count pos, nz list.
// ---------------------------------------------------------------------------
__global__ void epilogue_kernel(const float* __restrict__ bias,
                                float* __restrict__ out) {
    int i = blockIdx.x * blockDim.x + threadIdx.x;   // one float4
    const int total4 = (int)(N_TV / 4);
    int pos = 0;
    if (i < total4) {
        int row = i / (DOUT / 4);
        int c4  = i - row * (DOUT / 4);
        float4 s = *((const float4*)(g_sfast + (size_t)row * DOUT) + c4);
        float4 b = *((const float4*)bias + c4);
        float sv[4] = {s.x, s.y, s.z, s.w};
        float bv[4] = {b.x, b.y, b.z, b.w};
        float tv[4];
        ushort4 kv;
        unsigned short* kp = (unsigned short*)&kv;
#pragma unroll
        for (int e = 0; e < 4; e++) {
            __half hmm = __float2half(sv[e]);
            float tvf = __half2float(hmm) + bv[e];
            __half h = __float2half(tvf);
            tv[e] = __half2float(h);
            kp[e] = (unsigned short)key16f(tv[e]);
            pos += (tv[e] > 0.0f) ? 1 : 0;
            if (fabsf(tv[e]) < NZ_TVMAX) {   // tiny => always within T_FLAG of midpoint
                int idx = atomicAdd(&g_nz_cnt, 1);
                if (idx < LIST_CAP) g_nz[idx] = make_int2(row, c4 * 4 + e);
            }
        }
        *((float4*)(out + OFF_TV + (size_t)row * DOUT) + c4) =
            make_float4(tv[0], tv[1], tv[2], tv[3]);
        *((ushort4*)(g_key + (size_t)row * DOUT) + c4) = kv;
    }
#pragma unroll
    for (int off = 16; off; off >>= 1) pos += __shfl_down_sync(~0u, pos, off);
    __shared__ int spos[8];
    if ((threadIdx.x & 31) == 0) spos[threadIdx.x >> 5] = pos;
    __syncthreads();
    if (threadIdx.x == 0) {
        int t = 0;
        for (int k = 0; k < 8; k++) t += spos[k];
        if (t) atomicAdd(&g_pos, t);
    }
}

// ---------------------------------------------------------------------------
// Exact-chain recompute (round-7-bit-identical): ascending k, kc=320 panels.
// Reads f16 mirrors (exact same values, half the bytes). Patches tv + key.
// ---------------------------------------------------------------------------
__global__ void recompute_list_kernel(const float* __restrict__ bias,
                                      float* __restrict__ out, int which) {
    int cnt = (which == 0) ? g_nz_cnt : g_bd_cnt;
    if (cnt > LIST_CAP) cnt = LIST_CAP;
    const int2* list = (which == 0) ? g_nz : g_bd;
    int posDelta = 0;

    for (int idx = blockIdx.x * blockDim.x + threadIdx.x; idx < cnt;
         idx += gridDim.x * blockDim.x) {
        int row = list[idx].x, col = list[idx].y;
        const __half* xp = g_xh + (size_t)row * DIN;
        const __half* wp = g_wh + (size_t)col * DIN;
        float accT = 0.0f;
        int k = 0;
#pragma unroll 1
        for (int t = 0; t < 13; t++) {
            int kend = (t < 12) ? (t + 1) * 320 : DIN;
            float accC = 0.0f;
#pragma unroll 1
            for (; k < kend; k += 16) {
                uint4 xa = *(const uint4*)(xp + k);
                uint4 wa = *(const uint4*)(wp + k);
                uint4 xb = *(const uint4*)(xp + k + 8);
                uint4 wb = *(const uint4*)(wp + k + 8);
#pragma unroll
                for (int q = 0; q < 4; q++) {
                    float2 xf = __half22float2(((const __half2*)&xa)[q]);
                    float2 wf = __half22float2(((const __half2*)&wa)[q]);
                    accC = __fmaf_rn(xf.x, wf.x, accC);
                    accC = __fmaf_rn(xf.y, wf.y, accC);
                }
#pragma unroll
                for (int q = 0; q < 4; q++) {
                    float2 xf = __half22float2(((const __half2*)&xb)[q]);
                    float2 wf = __half22float2(((const __half2*)&wb)[q]);
                    accC = __fmaf_rn(xf.x, wf.x, accC);
                    accC = __fmaf_rn(xf.y, wf.y, accC);
                }
            }
            accT = accT + accC;
        }
        __half hmm = __float2half(accT);
        float tvf = __half2float(hmm) + bias[col];
        __half h = __float2half(tvf);
        float hv = __half2float(h);
        size_t o = (size_t)row * DOUT + col;
        float old = out[OFF_TV + o];
        if (which == 0)
            posDelta += ((hv > 0.0f) ? 1 : 0) - ((old > 0.0f) ? 1 : 0);
        out[OFF_TV + o] = hv;
        g_key[o] = (unsigned short)key16f(hv);
    }
    if (which == 0) {
#pragma unroll
        for (int off = 16; off; off >>= 1)
            posDelta += __shfl_down_sync(~0u, posDelta, off);
        if ((threadIdx.x & 31) == 0 && posDelta != 0) atomicAdd(&g_pos, posDelta);
    }
}

// ---------------------------------------------------------------------------
__global__ void limit_kernel() {
    g_limit = (int)floorf((0.2f * (float)g_pos) / 2048.0f);
}

// ---------------------------------------------------------------------------
// Phase A: per row (keys only), fast threshold K; collect flagged band elems.
// ---------------------------------------------------------------------------
__global__ void topmask_find_kernel() {
    int row = blockIdx.x;
    int limit = g_limit;
    if (limit <= 0) return;

    __shared__ int hist[256];
    __shared__ int sB, sChi, sK;
    int tid = threadIdx.x;
    const unsigned short* kr = g_key + (size_t)row * DOUT;

    hist[tid] = 0;
    __syncthreads();
    for (int j = tid; j < DOUT; j += 256)
        atomicAdd(&hist[kr[j] >> 8], 1);
    __syncthreads();
    if (tid == 0) {
        int c = 0, b = 255;
        for (; b > 0; b--) {
            if (c + hist[b] >= limit) break;
            c += hist[b];
        }
        sB = b; sChi = c;
    }
    __syncthreads();
    int b = sB, chi = sChi;

    hist[tid] = 0;
    __syncthreads();
    for (int j = tid; j < DOUT; j += 256) {
        unsigned u = kr[j];
        if ((int)(u >> 8) == b) atomicAdd(&hist[u & 255], 1);
    }
    __syncthreads();
    if (tid == 0) {
        int c = chi, lb = 255;
        for (; lb > 0; lb--) {
            if (c + hist[lb] >= limit) break;
            c += hist[lb];
        }
        sK = (b << 8) | lb;
    }
    __syncthreads();
    int K = sK;

    for (int j = tid; j < DOUT; j += 256) {
        int key = (int)kr[j];
        if (key >= K - BAND && key <= K + BAND) {
            float s = g_sfast[(size_t)row * DOUT + j];
            if (unsafe_val(s)) {
                int idx = atomicAdd(&g_bd_cnt, 1);
                if (idx < LIST_CAP) g_bd[idx] = make_int2(row, j);
            }
        }
    }
}

// ---------------------------------------------------------------------------
// Phase B: exact per-row top-limit selection on corrected keys; counts += mask.
// ---------------------------------------------------------------------------
__global__ void topmask_kernel() {
    int row = blockIdx.x;
    int limit = g_limit;
    if (limit <= 0) return;

    __shared__ int hist[256];
    __shared__ int scan[256];
    __shared__ int sB, sChi, sK, sNeed;
    int tid = threadIdx.x;
    const unsigned short* kr = g_key + (size_t)row * DOUT;

    hist[tid] = 0;
    __syncthreads();
    for (int j = tid; j < DOUT; j += 256)
        atomicAdd(&hist[kr[j] >> 8], 1);
    __syncthreads();
    if (tid == 0) {
        int c = 0, b = 255;
        for (; b > 0; b--) {
            if (c + hist[b] >= limit) break;
            c += hist[b];
        }
        sB = b; sChi = c;
    }
    __syncthreads();
    int b = sB, chi = sChi;

    hist[tid] = 0;
    __syncthreads();
    for (int j = tid; j < DOUT; j += 256) {
        unsigned u = kr[j];
        if ((int)(u >> 8) == b) atomicAdd(&hist[u & 255], 1);
    }
    __syncthreads();
    if (tid == 0) {
        int c = chi, lb = 255;
        for (; lb > 0; lb--) {
            if (c + hist[lb] >= limit) break;
            c += hist[lb];
        }
        sK = (b << 8) | lb;
        sNeed = limit - c;
    }
    __syncthreads();
    unsigned K = (unsigned)sK;
    int need = sNeed;

    int j0 = tid * 43;
    int myTies = 0;
    for (int j = j0; j < j0 + 43; j++) {
        unsigned u = kr[j];
        if (u > K) atomicAdd(&g_counts[j], 1);
        else if (u == K) myTies++;
    }
    scan[tid] = myTies;
    __syncthreads();
    for (int off = 1; off < 256; off <<= 1) {
        int t = (tid >= off) ? scan[tid - off] : 0;
        __syncthreads();
        scan[tid] += t;
        __syncthreads();
    }
    int rank = scan[tid] - myTies;
    if (myTies > 0) {
        for (int j = j0; j < j0 + 43; j++) {
            if (kr[j] == K) {
                if (rank < need) atomicAdd(&g_counts[j], 1);
                rank++;
            }
        }
    }
}

// ---------------------------------------------------------------------------
__global__ void sort_kernel(const float* __restrict__ bias, float* __restrict__ out) {
    extern __shared__ unsigned keys[];
    int tid = threadIdx.x;
    for (int i = tid; i < 16384; i += 1024) {
        int cnt = (i < DOUT) ? g_counts[i] : 0;
        keys[i] = ((unsigned)cnt << 14) | (unsigned)(16383 - i);
    }
    __syncthreads();
    for (unsigned k = 2; k <= 16384; k <<= 1) {
        for (unsigned j = k >> 1; j > 0; j >>= 1) {
            for (int i = tid; i < 16384; i += 1024) {
                unsigned ixj = (unsigned)i ^ j;
                if (ixj > (unsigned)i) {
                    unsigned a = keys[i], c = keys[ixj];
                    bool desc = ((i & k) == 0);
                    if (desc ? (a < c) : (a > c)) { keys[i] = c; keys[ixj] = a; }
                }
            }
            __syncthreads();
        }
    }
    for (int i = tid; i < REMAINED; i += 1024) {
        int idx = 16383 - (int)(keys[i] & 16383u);
        g_indices[i] = idx;
        out[OFF_BIAS + i] = bias[idx];
        out[OFF_IDX + i]  = (float)idx;
    }
}

// ---------------------------------------------------------------------------
__global__ void gather_kernel(const float* __restrict__ w, float* __restrict__ out) {
    int i = blockIdx.x * blockDim.x + threadIdx.x;
    const int total8 = REMAINED * (DIN / 8);
    if (i >= total8) return;
    int r = i / (DIN / 8);
    int c8 = i % (DIN / 8);
    int src = g_indices[r];
    const float* s = w + (size_t)src * DIN + (size_t)c8 * 8;
    float* o = out + OFF_W + (size_t)r * DIN + (size_t)c8 * 8;
    float4 v0 = *(const float4*)(s);
    float4 v1 = *(const float4*)(s + 4);
    *(float4*)(o)     = v0;
    *(float4*)(o + 4) = v1;
}

// ---------------------------------------------------------------------------
extern "C" void kernel_launch(void* const* d_in, const int* in_sizes, int n_in,
                              void* d_out, int out_size) {
    const float* x    = (const float*)d_in[0];
    const float* w    = (const float*)d_in[1];
    const float* bias = (const float*)d_in[2];
    float* out = (float*)d_out;

    static __half* xh_p = nullptr;
    static __half* wh_p = nullptr;
    static float* sfast_p = nullptr;
    if (!xh_p) {
        cudaGetSymbolAddress((void**)&xh_p, g_xh);
        cudaGetSymbolAddress((void**)&wh_p, g_wh);
        cudaGetSymbolAddress((void**)&sfast_p, g_sfast);
    }

    const int GEMM_SMEM = 2 * (GBM + GBN) * PAD * 2;  // 110592 B
    cudaFuncSetAttribute(gemm_fast_kernel, cudaFuncAttributeMaxDynamicSharedMemorySize, GEMM_SMEM);
    cudaFuncSetAttribute(sort_kernel, cudaFuncAttributeMaxDynamicSharedMemorySize, 65536);

    init_kernel<<<(DOUT + 255) / 256, 256>>>();
    convert_kernel<<<(S_DIM * DIN / 8 + 255) / 256, 256>>>(x, xh_p, S_DIM * DIN / 8);
    convert_kernel<<<(DOUT * DIN / 8 + 255) / 256, 256>>>(w, wh_p, DOUT * DIN / 8);
    gemm_fast_kernel<<<dim3(DOUT / GBN, S_DIM / GBM), 256, GEMM_SMEM>>>(sfast_p);
    epilogue_kernel<<<(int)((N_TV / 4 + 255) / 256), 256>>>(bias, out);
    recompute_list_kernel<<<64, 256>>>(bias, out, 0);
    limit_kernel<<<1, 1>>>();
    topmask_find_kernel<<<S_DIM, 256>>>();
    recompute_list_kernel<<<64, 256>>>(bias, out, 1);
    topmask_kernel<<<S_DIM, 256>>>();
    sort_kernel<<<1, 1024, 65536>>>(bias, out);
    gather_kernel<<<(REMAINED * (DIN / 8) + 255) / 256, 256>>>(w, out);
}